// round 4
// baseline (speedup 1.0000x reference)
#include <cuda_runtime.h>
#include <math.h>

// ---------------------------------------------------------------------------
// Problem: SelfAttnV3  B=8, N=2048, D=1024
// inputs: x[8,2048,1024] f32, mask[8,2048,2048] i32, W_qkv[1024,3072] f32,
//         b_qkv[3072] f32, W_out[1024,1024] f32, b_out[1024] f32
// output: [8,2048,1024] f32
// ---------------------------------------------------------------------------

#define BB 8
#define NN 2048
#define DD 1024

// Scratch (device globals -- no allocation allowed)
__device__ float g_qkv[(long long)BB * NN * 3 * DD];      // 192 MB
__device__ float g_scores[(long long)BB * NN * NN];       // 128 MB
__device__ float g_attn[(long long)BB * NN * DD];         // 64 MB

// ---------------------------------------------------------------------------
// Generic tiled SGEMM:  C = alpha * A @ op(B) (+ bias)
//  A: M x K, row-major, lda
//  B: if TRANS_B: N x K row-major (we use B^T), else K x N row-major
//  C: M x N, row-major, ldc
//  Batched over blockIdx.z with element strides.
//  All dims assumed multiples of tile sizes (true for this problem).
// ---------------------------------------------------------------------------
#define BM 128
#define BN 128
#define BK 16
#define TM 8
#define TN 8

template <bool TRANS_B, bool HAS_BIAS>
__global__ __launch_bounds__(256, 2)
void gemm_kernel(const float* __restrict__ A, const float* __restrict__ B,
                 const float* __restrict__ bias, float* __restrict__ C,
                 int K, int lda, int ldb, int ldc,
                 long long strideA, long long strideB, long long strideC,
                 float alpha)
{
    __shared__ float As[BK][BM + 4];
    __shared__ float Bs[BK][BN + 4];

    const int bx = blockIdx.x;   // N tile
    const int by = blockIdx.y;   // M tile
    const int bz = blockIdx.z;   // batch

    A += (long long)bz * strideA + (long long)by * BM * lda;
    B += (long long)bz * strideB;
    C += (long long)bz * strideC + (long long)by * BM * ldc + (long long)bx * BN;
    if (TRANS_B) B += (long long)bx * BN * ldb;
    else         B += bx * BN;

    const int tid = threadIdx.x;
    const int tx = tid & 15;     // 0..15  -> N
    const int ty = tid >> 4;     // 0..15  -> M

    float acc[TM][TN];
#pragma unroll
    for (int i = 0; i < TM; i++)
#pragma unroll
        for (int j = 0; j < TN; j++) acc[i][j] = 0.0f;

    // A-tile loading: thread -> (row = tid/4 [+64], 4 cols at (tid%4)*4)
    const int arow = tid >> 2;          // 0..63
    const int acol = (tid & 3) * 4;     // 0,4,8,12
    // B-tile loading (KxN case): row = tid/32 [+8], col = (tid%32)*4
    const int brow = tid >> 5;          // 0..7
    const int bcol = (tid & 31) * 4;

    for (int k0 = 0; k0 < K; k0 += BK) {
        // ---- load A tile (store transposed: As[k][m]) ----
#pragma unroll
        for (int r = 0; r < 2; r++) {
            const int m = arow + r * 64;
            const float4 v = *reinterpret_cast<const float4*>(
                &A[(long long)m * lda + k0 + acol]);
            As[acol + 0][m] = v.x;
            As[acol + 1][m] = v.y;
            As[acol + 2][m] = v.z;
            As[acol + 3][m] = v.w;
        }
        // ---- load B tile ----
        if (TRANS_B) {
#pragma unroll
            for (int r = 0; r < 2; r++) {
                const int n = arow + r * 64;
                const float4 v = *reinterpret_cast<const float4*>(
                    &B[(long long)n * ldb + k0 + acol]);
                Bs[acol + 0][n] = v.x;
                Bs[acol + 1][n] = v.y;
                Bs[acol + 2][n] = v.z;
                Bs[acol + 3][n] = v.w;
            }
        } else {
#pragma unroll
            for (int r = 0; r < 2; r++) {
                const int kk = brow + r * 8;
                const float4 v = *reinterpret_cast<const float4*>(
                    &B[(long long)(k0 + kk) * ldb + bcol]);
                *reinterpret_cast<float4*>(&Bs[kk][bcol]) = v;
            }
        }
        __syncthreads();

        // ---- compute ----
#pragma unroll
        for (int k = 0; k < BK; k++) {
            float a[TM], b[TN];
#pragma unroll
            for (int i = 0; i < TM; i += 4)
                *reinterpret_cast<float4*>(&a[i]) =
                    *reinterpret_cast<const float4*>(&As[k][ty * TM + i]);
#pragma unroll
            for (int j = 0; j < TN; j += 4)
                *reinterpret_cast<float4*>(&b[j]) =
                    *reinterpret_cast<const float4*>(&Bs[k][tx * TN + j]);
#pragma unroll
            for (int i = 0; i < TM; i++)
#pragma unroll
                for (int j = 0; j < TN; j++)
                    acc[i][j] = fmaf(a[i], b[j], acc[i][j]);
        }
        __syncthreads();
    }

    // ---- epilogue ----
#pragma unroll
    for (int i = 0; i < TM; i++) {
        float* crow = C + (long long)(ty * TM + i) * ldc + tx * TN;
#pragma unroll
        for (int j = 0; j < TN; j += 4) {
            float4 v;
            v.x = acc[i][j + 0] * alpha;
            v.y = acc[i][j + 1] * alpha;
            v.z = acc[i][j + 2] * alpha;
            v.w = acc[i][j + 3] * alpha;
            if (HAS_BIAS) {
                const float4 bb = *reinterpret_cast<const float4*>(
                    &bias[bx * BN + tx * TN + j]);
                v.x += bb.x; v.y += bb.y; v.z += bb.z; v.w += bb.w;
            }
            *reinterpret_cast<float4*>(&crow[j]) = v;
        }
    }
}

// ---------------------------------------------------------------------------
// Fused double-softmax with mask, in place on the score matrix.
//   p = softmax(s)              (row of 2048)
//   t = mask ? exp(p - max_unmasked(p)) : 0
//   w = t / sum(t)
// One block (256 threads) per row; 8 elements per thread in registers.
// ---------------------------------------------------------------------------
__device__ __forceinline__ float warpMax(float v) {
#pragma unroll
    for (int o = 16; o > 0; o >>= 1) v = fmaxf(v, __shfl_xor_sync(0xffffffffu, v, o));
    return v;
}
__device__ __forceinline__ float warpSum(float v) {
#pragma unroll
    for (int o = 16; o > 0; o >>= 1) v += __shfl_xor_sync(0xffffffffu, v, o);
    return v;
}

__device__ __forceinline__ float blockMax(float v, float* s) {
    const int w = threadIdx.x >> 5, l = threadIdx.x & 31;
    v = warpMax(v);
    __syncthreads();
    if (l == 0) s[w] = v;
    __syncthreads();
    float r = s[0];
#pragma unroll
    for (int i = 1; i < 8; i++) r = fmaxf(r, s[i]);
    return r;
}
__device__ __forceinline__ float blockSum(float v, float* s) {
    const int w = threadIdx.x >> 5, l = threadIdx.x & 31;
    v = warpSum(v);
    __syncthreads();
    if (l == 0) s[w] = v;
    __syncthreads();
    float r = s[0];
#pragma unroll
    for (int i = 1; i < 8; i++) r += s[i];
    return r;
}

__global__ __launch_bounds__(256)
void softmax_mask_kernel(float* __restrict__ S, const int* __restrict__ mask)
{
    __shared__ float red[8];

    const long long row = (long long)blockIdx.y * NN + blockIdx.x; // b*N + q
    float* srow = S + row * NN;
    const int* mrow = mask + row * NN;

    const int base = threadIdx.x * 8;

    // load 8 scores
    float v[8];
    *reinterpret_cast<float4*>(&v[0]) = *reinterpret_cast<const float4*>(&srow[base]);
    *reinterpret_cast<float4*>(&v[4]) = *reinterpret_cast<const float4*>(&srow[base + 4]);

    // ---- first softmax ----
    float m = v[0];
#pragma unroll
    for (int i = 1; i < 8; i++) m = fmaxf(m, v[i]);
    m = blockMax(m, red);

    float p[8];
    float lsum = 0.0f;
#pragma unroll
    for (int i = 0; i < 8; i++) { p[i] = __expf(v[i] - m); lsum += p[i]; }
    const float inv1 = 1.0f / blockSum(lsum, red);
#pragma unroll
    for (int i = 0; i < 8; i++) p[i] *= inv1;

    // ---- mask + second softmax ----
    int mk[8];
    *reinterpret_cast<int4*>(&mk[0]) = *reinterpret_cast<const int4*>(&mrow[base]);
    *reinterpret_cast<int4*>(&mk[4]) = *reinterpret_cast<const int4*>(&mrow[base + 4]);

    float m2 = -3.0e38f;
#pragma unroll
    for (int i = 0; i < 8; i++) if (mk[i] != 0) m2 = fmaxf(m2, p[i]);
    m2 = blockMax(m2, red);

    float t[8];
    float lsum2 = 0.0f;
#pragma unroll
    for (int i = 0; i < 8; i++) {
        t[i] = (mk[i] != 0) ? __expf(p[i] - m2) : 0.0f;
        lsum2 += t[i];
    }
    const float inv2 = 1.0f / blockSum(lsum2, red);

    float w[8];
#pragma unroll
    for (int i = 0; i < 8; i++) w[i] = t[i] * inv2;

    *reinterpret_cast<float4*>(&srow[base])     = *reinterpret_cast<float4*>(&w[0]);
    *reinterpret_cast<float4*>(&srow[base + 4]) = *reinterpret_cast<float4*>(&w[4]);
}

// ---------------------------------------------------------------------------
// Launch
// ---------------------------------------------------------------------------
extern "C" void kernel_launch(void* const* d_in, const int* in_sizes, int n_in,
                              void* d_out, int out_size)
{
    (void)in_sizes; (void)n_in; (void)out_size;

    const float* x     = (const float*)d_in[0];
    const int*   mask  = (const int*)  d_in[1];
    const float* Wqkv  = (const float*)d_in[2];
    const float* bqkv  = (const float*)d_in[3];
    const float* Wout  = (const float*)d_in[4];
    const float* bout  = (const float*)d_in[5];
    float* out = (float*)d_out;

    float *qkv, *scores, *attn;
    cudaGetSymbolAddress((void**)&qkv,    g_qkv);
    cudaGetSymbolAddress((void**)&scores, g_scores);
    cudaGetSymbolAddress((void**)&attn,   g_attn);

    const long long sQKV = (long long)NN * 3 * DD;   // per-batch qkv stride
    const long long sSC  = (long long)NN * NN;       // per-batch scores stride
    const long long sAT  = (long long)NN * DD;       // per-batch attn stride

    // 1) qkv = x @ W_qkv + b_qkv        [16384,3072] = [16384,1024]@[1024,3072]
    gemm_kernel<false, true><<<dim3(3 * DD / BN, BB * NN / BM, 1), 256>>>(
        x, Wqkv, bqkv, qkv, DD, DD, 3 * DD, 3 * DD, 0, 0, 0, 1.0f);

    // 2) scores[b] = Q[b] @ K[b]^T * (1/32)   batched [2048,2048] k=1024
    gemm_kernel<true, false><<<dim3(NN / BN, NN / BM, BB), 256>>>(
        qkv, qkv + DD, nullptr, scores, DD, 3 * DD, 3 * DD, NN,
        sQKV, sQKV, sSC, 0.03125f);

    // 3) fused double softmax + mask, in place
    softmax_mask_kernel<<<dim3(NN, BB), 256>>>(scores, mask);

    // 4) attn[b] = W[b] @ V[b]   batched [2048,1024] k=2048
    gemm_kernel<false, false><<<dim3(DD / BN, NN / BM, BB), 256>>>(
        scores, qkv + 2 * DD, nullptr, attn, NN, NN, 3 * DD, DD,
        sSC, sQKV, sAT, 1.0f);

    // 5) out = attn @ W_out + b_out     [16384,1024] k=1024
    gemm_kernel<false, true><<<dim3(DD / BN, BB * NN / BM, 1), 256>>>(
        attn, Wout, bout, out, DD, DD, DD, DD, 0, 0, 0, 1.0f);
}

// round 7
// speedup vs baseline: 2.4450x; 2.4450x over previous
#include <cuda_runtime.h>
#include <cuda_bf16.h>
#include <cstdint>
#include <cstring>
#include <math.h>

// ---------------------------------------------------------------------------
// SelfAttnV3  B=8, N=2048, D=1024
// HMMA (mma.sync bf16, 3-term split precision) GEMMs -- sm_103 base target.
// ---------------------------------------------------------------------------
#define BB 8
#define NN 2048
#define DD 1024

// ------------------------- device scratch (no allocs) ----------------------
__device__ float g_qkv[(long long)BB * NN * 3 * DD];      // 192 MB
__device__ float g_scores[(long long)BB * NN * NN];       // 128 MB
__device__ float g_attn[(long long)BB * NN * DD];         // 64 MB

__device__ __nv_bfloat16 g_xh[(long long)BB * NN * DD];
__device__ __nv_bfloat16 g_xl[(long long)BB * NN * DD];
__device__ __nv_bfloat16 g_wqt_h[(long long)3 * DD * DD];
__device__ __nv_bfloat16 g_wqt_l[(long long)3 * DD * DD];
__device__ __nv_bfloat16 g_wot_h[(long long)DD * DD];
__device__ __nv_bfloat16 g_wot_l[(long long)DD * DD];
__device__ __nv_bfloat16 g_qh[(long long)BB * NN * DD];
__device__ __nv_bfloat16 g_ql[(long long)BB * NN * DD];
__device__ __nv_bfloat16 g_kh[(long long)BB * NN * DD];
__device__ __nv_bfloat16 g_kl[(long long)BB * NN * DD];
__device__ __nv_bfloat16 g_vth[(long long)BB * DD * NN];
__device__ __nv_bfloat16 g_vtl[(long long)BB * DD * NN];
__device__ __nv_bfloat16 g_ph[(long long)BB * NN * NN];
__device__ __nv_bfloat16 g_pl[(long long)BB * NN * NN];
__device__ __nv_bfloat16 g_ath[(long long)BB * NN * DD];
__device__ __nv_bfloat16 g_atl[(long long)BB * NN * DD];

// ------------------------------ PTX helpers --------------------------------
__device__ __forceinline__ uint32_t smem_u32(const void* p) {
    uint32_t a;
    asm("{ .reg .u64 t; cvta.to.shared.u64 t, %1; cvt.u32.u64 %0, t; }"
        : "=r"(a) : "l"(p));
    return a;
}

#define CP_ASYNC16(dst, src) \
    asm volatile("cp.async.cg.shared.global [%0], [%1], 16;" :: "r"(dst), "l"(src) : "memory")
#define CP_ASYNC_COMMIT() asm volatile("cp.async.commit_group;" ::: "memory")
#define CP_ASYNC_WAIT(n)  asm volatile("cp.async.wait_group %0;" :: "n"(n) : "memory")

__device__ __forceinline__ void ldsm4(uint32_t r[4], uint32_t addr) {
    asm volatile("ldmatrix.sync.aligned.m8n8.x4.shared.b16 {%0,%1,%2,%3}, [%4];"
                 : "=r"(r[0]), "=r"(r[1]), "=r"(r[2]), "=r"(r[3]) : "r"(addr));
}

__device__ __forceinline__ void mma_bf16(float c[4], const uint32_t a[4],
                                         uint32_t b0, uint32_t b1) {
    asm volatile(
        "mma.sync.aligned.m16n8k16.row.col.f32.bf16.bf16.f32 "
        "{%0,%1,%2,%3}, {%4,%5,%6,%7}, {%8,%9}, {%0,%1,%2,%3};"
        : "+f"(c[0]), "+f"(c[1]), "+f"(c[2]), "+f"(c[3])
        : "r"(a[0]), "r"(a[1]), "r"(a[2]), "r"(a[3]), "r"(b0), "r"(b1));
}

// ------------------------------ bf16 split helpers -------------------------
__device__ __forceinline__ void split4_store(__nv_bfloat16* ph, __nv_bfloat16* pl, float4 v)
{
    __nv_bfloat162 h01 = __floats2bfloat162_rn(v.x, v.y);
    __nv_bfloat162 h23 = __floats2bfloat162_rn(v.z, v.w);
    float2 f01 = __bfloat1622float2(h01);
    float2 f23 = __bfloat1622float2(h23);
    __nv_bfloat162 l01 = __floats2bfloat162_rn(v.x - f01.x, v.y - f01.y);
    __nv_bfloat162 l23 = __floats2bfloat162_rn(v.z - f23.x, v.w - f23.y);
    uint2 uh, ul;
    memcpy(&uh.x, &h01, 4); memcpy(&uh.y, &h23, 4);
    memcpy(&ul.x, &l01, 4); memcpy(&ul.y, &l23, 4);
    *reinterpret_cast<uint2*>(ph) = uh;
    *reinterpret_cast<uint2*>(pl) = ul;
}

// ---------------------------------------------------------------------------
// HMMA GEMM: C[M,N] (+bias) = alpha * A @ B^T with split-bf16 operands.
//   A: hi/lo bf16, M rows, K-major, ld = lda
//   B: hi/lo bf16, N rows, K-major, ld = ldb
// CTA tile 128x128, BK=64, double-buffered cp.async.
// SMEM per stage: Ah | Al | Bh | Bl, each 128 rows x 128B, xor-swizzled.
// 8 warps: warp (wm = wid&3, wn = wid>>2) owns 32(m) x 64(n).
// ---------------------------------------------------------------------------
#define GEMM_SMEM_BYTES (2 * 4 * 16384)

__device__ __forceinline__ void load_stage(uint32_t sbase,
    const __nv_bfloat16* Ah, const __nv_bfloat16* Al,
    const __nv_bfloat16* Bh, const __nv_bfloat16* Bl,
    int lda, int ldb, int k0, int tid)
{
#pragma unroll
    for (int i = 0; i < 4; i++) {
        const int idx = i * 256 + tid;
        const int row = idx >> 3;                       // 0..127
        const int cb  = (idx & 7) << 4;                 // 16B chunk
        const uint32_t soff = row * 128 + (cb ^ ((row & 7) << 4));
        const long long ea = (long long)row * lda + k0 + (cb >> 1);
        const long long eb = (long long)row * ldb + k0 + (cb >> 1);
        CP_ASYNC16(sbase +         soff, Ah + ea);
        CP_ASYNC16(sbase + 16384 + soff, Al + ea);
        CP_ASYNC16(sbase + 32768 + soff, Bh + eb);
        CP_ASYNC16(sbase + 49152 + soff, Bl + eb);
    }
}

template <bool HAS_BIAS>
__global__ void __launch_bounds__(256, 1)
tc_gemm_kernel(const __nv_bfloat16* __restrict__ Ah, const __nv_bfloat16* __restrict__ Al,
               const __nv_bfloat16* __restrict__ Bh, const __nv_bfloat16* __restrict__ Bl,
               const float* __restrict__ bias, float* __restrict__ C,
               int K, int lda, int ldb, int ldc,
               long long sA, long long sB, long long sC, float alpha)
{
    extern __shared__ char smem[];
    const uint32_t sb = smem_u32(smem);
    const int tid  = threadIdx.x;
    const int lane = tid & 31;
    const int wid  = tid >> 5;
    const int wm = wid & 3;        // 4 warps along M
    const int wn = wid >> 2;       // 2 warps along N

    const int bx = blockIdx.x, by = blockIdx.y, bz = blockIdx.z;
    const long long aOff = (long long)bz * sA + (long long)by * 128 * lda;
    const long long bOff = (long long)bz * sB + (long long)bx * 128 * ldb;
    Ah += aOff; Al += aOff; Bh += bOff; Bl += bOff;
    C  += (long long)bz * sC + (long long)by * 128 * ldc + (long long)bx * 128;

    float acc[2][8][4];
#pragma unroll
    for (int i = 0; i < 2; i++)
#pragma unroll
        for (int j = 0; j < 8; j++)
#pragma unroll
            for (int q = 0; q < 4; q++) acc[i][j][q] = 0.0f;

    const int T = K >> 6;

    load_stage(sb, Ah, Al, Bh, Bl, lda, ldb, 0, tid);
    CP_ASYNC_COMMIT();

    for (int t = 0; t < T; t++) {
        if (t + 1 < T) {
            load_stage(sb + (((t + 1) & 1) << 16), Ah, Al, Bh, Bl,
                       lda, ldb, (t + 1) << 6, tid);
            CP_ASYNC_COMMIT();
            CP_ASYNC_WAIT(1);
        } else {
            CP_ASYNC_WAIT(0);
        }
        __syncthreads();

        const uint32_t st = sb + ((t & 1) << 16);
#pragma unroll
        for (int k16 = 0; k16 < 4; k16++) {
            const int cbase = k16 * 32 + ((lane >> 4) << 4);

            uint32_t ah[2][4], al[2][4];
#pragma unroll
            for (int mt = 0; mt < 2; mt++) {
                const int row = wm * 32 + mt * 16 + (lane & 15);
                const uint32_t off = row * 128 + (cbase ^ ((row & 7) << 4));
                ldsm4(ah[mt], st + off);
                ldsm4(al[mt], st + 16384 + off);
            }
            uint32_t bh[4][4], bl[4][4];
#pragma unroll
            for (int ntp = 0; ntp < 4; ntp++) {
                const int row = wn * 64 + ntp * 16 + (lane & 15);
                const uint32_t off = row * 128 + (cbase ^ ((row & 7) << 4));
                ldsm4(bh[ntp], st + 32768 + off);
                ldsm4(bl[ntp], st + 49152 + off);
            }
#pragma unroll
            for (int mt = 0; mt < 2; mt++)
#pragma unroll
                for (int ntp = 0; ntp < 4; ntp++)
#pragma unroll
                    for (int sub = 0; sub < 2; sub++) {
                        float* c = acc[mt][ntp * 2 + sub];
                        mma_bf16(c, ah[mt], bh[ntp][sub], bh[ntp][sub + 2]);
                        mma_bf16(c, ah[mt], bl[ntp][sub], bl[ntp][sub + 2]);
                        mma_bf16(c, al[mt], bh[ntp][sub], bh[ntp][sub + 2]);
                    }
        }
        __syncthreads();
    }

    // ---- epilogue ----
    const int rbase = wm * 32 + (lane >> 2);
    const int cbase = wn * 64 + (lane & 3) * 2;
#pragma unroll
    for (int mt = 0; mt < 2; mt++)
#pragma unroll
        for (int nt = 0; nt < 8; nt++) {
            const float* a = acc[mt][nt];
            const int m = rbase + mt * 16;
            const int n = cbase + nt * 8;
            float2 v0 = make_float2(a[0] * alpha, a[1] * alpha);
            float2 v1 = make_float2(a[2] * alpha, a[3] * alpha);
            if (HAS_BIAS) {
                const float b0 = bias[(long long)bx * 128 + n];
                const float b1 = bias[(long long)bx * 128 + n + 1];
                v0.x += b0; v0.y += b1; v1.x += b0; v1.y += b1;
            }
            *reinterpret_cast<float2*>(&C[(long long)m * ldc + n]) = v0;
            *reinterpret_cast<float2*>(&C[(long long)(m + 8) * ldc + n]) = v1;
        }
}

// ---------------------------------------------------------------------------
// elementwise fp32 -> bf16 hi/lo split
// ---------------------------------------------------------------------------
__global__ void __launch_bounds__(256)
split_kernel(const float* __restrict__ in, __nv_bfloat16* __restrict__ oh,
             __nv_bfloat16* __restrict__ ol, long long n)
{
    const long long i = ((long long)blockIdx.x * 256 + threadIdx.x) * 4;
    if (i >= n) return;
    const float4 v = *reinterpret_cast<const float4*>(&in[i]);
    split4_store(oh + i, ol + i, v);
}

// ---------------------------------------------------------------------------
// transpose + split: out[c][r] = in[r][c]; out hi/lo bf16
// ---------------------------------------------------------------------------
__global__ void __launch_bounds__(256)
transpose_split_kernel(const float* __restrict__ in, int ld_in, long long strideIn,
                       __nv_bfloat16* __restrict__ oh, __nv_bfloat16* __restrict__ ol,
                       int ld_out, long long strideOut)
{
    __shared__ float t[32][33];
    const int bz = blockIdx.z;
    in += (long long)bz * strideIn;
    oh += (long long)bz * strideOut;
    ol += (long long)bz * strideOut;
    const int tx = threadIdx.x & 31, ty = threadIdx.x >> 5;
    const int r0 = blockIdx.y * 32, c0 = blockIdx.x * 32;
#pragma unroll
    for (int i = 0; i < 4; i++)
        t[ty + i * 8][tx] = in[(long long)(r0 + ty + i * 8) * ld_in + c0 + tx];
    __syncthreads();
#pragma unroll
    for (int i = 0; i < 4; i++) {
        const int oc = ty + i * 8;
        const float v = t[tx][oc];
        const __nv_bfloat16 h = __float2bfloat16_rn(v);
        const long long o = (long long)(c0 + oc) * ld_out + r0 + tx;
        oh[o] = h;
        ol[o] = __float2bfloat16_rn(v - __bfloat162float(h));
    }
}

// ---------------------------------------------------------------------------
// split Q,K rows out of qkv fp32 (row = b*N+n, 3072 wide)
// ---------------------------------------------------------------------------
__global__ void __launch_bounds__(256)
qk_split_kernel(const float* __restrict__ qkv,
                __nv_bfloat16* __restrict__ Qh, __nv_bfloat16* __restrict__ Ql,
                __nv_bfloat16* __restrict__ Kh, __nv_bfloat16* __restrict__ Kl)
{
    const long long row = blockIdx.x;
    const float* src = qkv + row * 3 * DD;
    const int idx = threadIdx.x * 4;
    const float4 q  = *reinterpret_cast<const float4*>(&src[idx]);
    const float4 kk = *reinterpret_cast<const float4*>(&src[DD + idx]);
    split4_store(Qh + row * DD + idx, Ql + row * DD + idx, q);
    split4_store(Kh + row * DD + idx, Kl + row * DD + idx, kk);
}

// ---------------------------------------------------------------------------
// fused double-softmax with mask; outputs bf16 hi/lo probs
// ---------------------------------------------------------------------------
__device__ __forceinline__ float warpMax(float v) {
#pragma unroll
    for (int o = 16; o > 0; o >>= 1) v = fmaxf(v, __shfl_xor_sync(0xffffffffu, v, o));
    return v;
}
__device__ __forceinline__ float warpSum(float v) {
#pragma unroll
    for (int o = 16; o > 0; o >>= 1) v += __shfl_xor_sync(0xffffffffu, v, o);
    return v;
}
__device__ __forceinline__ float blockMax(float v, float* s) {
    const int w = threadIdx.x >> 5, l = threadIdx.x & 31;
    v = warpMax(v);
    __syncthreads();
    if (l == 0) s[w] = v;
    __syncthreads();
    float r = s[0];
#pragma unroll
    for (int i = 1; i < 8; i++) r = fmaxf(r, s[i]);
    return r;
}
__device__ __forceinline__ float blockSum(float v, float* s) {
    const int w = threadIdx.x >> 5, l = threadIdx.x & 31;
    v = warpSum(v);
    __syncthreads();
    if (l == 0) s[w] = v;
    __syncthreads();
    float r = s[0];
#pragma unroll
    for (int i = 1; i < 8; i++) r += s[i];
    return r;
}

__global__ __launch_bounds__(256)
void softmax_mask_kernel(const float* __restrict__ S, const int* __restrict__ mask,
                         __nv_bfloat16* __restrict__ Ph, __nv_bfloat16* __restrict__ Pl)
{
    __shared__ float red[8];

    const long long row = (long long)blockIdx.y * NN + blockIdx.x;
    const float* srow = S + row * NN;
    const int* mrow = mask + row * NN;
    const int base = threadIdx.x * 8;

    float v[8];
    *reinterpret_cast<float4*>(&v[0]) = *reinterpret_cast<const float4*>(&srow[base]);
    *reinterpret_cast<float4*>(&v[4]) = *reinterpret_cast<const float4*>(&srow[base + 4]);

    float m = v[0];
#pragma unroll
    for (int i = 1; i < 8; i++) m = fmaxf(m, v[i]);
    m = blockMax(m, red);

    float p[8], lsum = 0.0f;
#pragma unroll
    for (int i = 0; i < 8; i++) { p[i] = __expf(v[i] - m); lsum += p[i]; }
    const float inv1 = 1.0f / blockSum(lsum, red);
#pragma unroll
    for (int i = 0; i < 8; i++) p[i] *= inv1;

    int mk[8];
    *reinterpret_cast<int4*>(&mk[0]) = *reinterpret_cast<const int4*>(&mrow[base]);
    *reinterpret_cast<int4*>(&mk[4]) = *reinterpret_cast<const int4*>(&mrow[base + 4]);

    float m2 = -3.0e38f;
#pragma unroll
    for (int i = 0; i < 8; i++) if (mk[i] != 0) m2 = fmaxf(m2, p[i]);
    m2 = blockMax(m2, red);

    float t[8], lsum2 = 0.0f;
#pragma unroll
    for (int i = 0; i < 8; i++) {
        t[i] = (mk[i] != 0) ? __expf(p[i] - m2) : 0.0f;
        lsum2 += t[i];
    }
    const float inv2 = 1.0f / blockSum(lsum2, red);

    float w[8];
#pragma unroll
    for (int i = 0; i < 8; i++) w[i] = t[i] * inv2;

    __nv_bfloat16* ph = Ph + row * NN + base;
    __nv_bfloat16* pl = Pl + row * NN + base;
    split4_store(ph,     pl,     *reinterpret_cast<float4*>(&w[0]));
    split4_store(ph + 4, pl + 4, *reinterpret_cast<float4*>(&w[4]));
}

// ---------------------------------------------------------------------------
// Launch
// ---------------------------------------------------------------------------
extern "C" void kernel_launch(void* const* d_in, const int* in_sizes, int n_in,
                              void* d_out, int out_size)
{
    (void)in_sizes; (void)n_in; (void)out_size;

    const float* x    = (const float*)d_in[0];
    const int*   mask = (const int*)  d_in[1];
    const float* Wqkv = (const float*)d_in[2];
    const float* bqkv = (const float*)d_in[3];
    const float* Wout = (const float*)d_in[4];
    const float* bout = (const float*)d_in[5];
    float* out = (float*)d_out;

    cudaFuncSetAttribute(tc_gemm_kernel<true>,
                         cudaFuncAttributeMaxDynamicSharedMemorySize, GEMM_SMEM_BYTES);
    cudaFuncSetAttribute(tc_gemm_kernel<false>,
                         cudaFuncAttributeMaxDynamicSharedMemorySize, GEMM_SMEM_BYTES);

    float *qkv, *scores, *attn;
    cudaGetSymbolAddress((void**)&qkv,    g_qkv);
    cudaGetSymbolAddress((void**)&scores, g_scores);
    cudaGetSymbolAddress((void**)&attn,   g_attn);
    __nv_bfloat16 *xh, *xl, *wqt_h, *wqt_l, *wot_h, *wot_l;
    __nv_bfloat16 *qh, *ql, *kh, *kl, *vth, *vtl, *ph, *pl, *ath, *atl;
    cudaGetSymbolAddress((void**)&xh, g_xh);     cudaGetSymbolAddress((void**)&xl, g_xl);
    cudaGetSymbolAddress((void**)&wqt_h, g_wqt_h); cudaGetSymbolAddress((void**)&wqt_l, g_wqt_l);
    cudaGetSymbolAddress((void**)&wot_h, g_wot_h); cudaGetSymbolAddress((void**)&wot_l, g_wot_l);
    cudaGetSymbolAddress((void**)&qh, g_qh);     cudaGetSymbolAddress((void**)&ql, g_ql);
    cudaGetSymbolAddress((void**)&kh, g_kh);     cudaGetSymbolAddress((void**)&kl, g_kl);
    cudaGetSymbolAddress((void**)&vth, g_vth);   cudaGetSymbolAddress((void**)&vtl, g_vtl);
    cudaGetSymbolAddress((void**)&ph, g_ph);     cudaGetSymbolAddress((void**)&pl, g_pl);
    cudaGetSymbolAddress((void**)&ath, g_ath);   cudaGetSymbolAddress((void**)&atl, g_atl);

    const long long nTok = (long long)BB * NN;           // 16384
    const long long sQ   = (long long)NN * DD;
    const long long sSC  = (long long)NN * NN;
    const long long sVT  = (long long)DD * NN;

    // 1) split x -> bf16 hi/lo
    split_kernel<<<(unsigned)(nTok * DD / 1024), 256>>>(x, xh, xl, nTok * DD);

    // 2) transpose+split weights
    transpose_split_kernel<<<dim3(3 * DD / 32, DD / 32, 1), 256>>>(
        Wqkv, 3 * DD, 0, wqt_h, wqt_l, DD, 0);
    transpose_split_kernel<<<dim3(DD / 32, DD / 32, 1), 256>>>(
        Wout, DD, 0, wot_h, wot_l, DD, 0);

    // 3) qkv = x @ W_qkv + b_qkv  (fp32 out)
    tc_gemm_kernel<true><<<dim3(3 * DD / 128, (unsigned)(nTok / 128), 1), 256,
                           GEMM_SMEM_BYTES>>>(
        xh, xl, wqt_h, wqt_l, bqkv, qkv, DD, DD, DD, 3 * DD, 0, 0, 0, 1.0f);

    // 4) split Q,K (K-major) and V (transposed)
    qk_split_kernel<<<(unsigned)nTok, 256>>>(qkv, qh, ql, kh, kl);
    transpose_split_kernel<<<dim3(DD / 32, NN / 32, BB), 256>>>(
        qkv + 2 * DD, 3 * DD, (long long)NN * 3 * DD, vth, vtl, NN, sVT);

    // 5) scores = Q @ K^T / 32  (fp32 out)
    tc_gemm_kernel<false><<<dim3(NN / 128, NN / 128, BB), 256, GEMM_SMEM_BYTES>>>(
        qh, ql, kh, kl, nullptr, scores, DD, DD, DD, NN, sQ, sQ, sSC, 0.03125f);

    // 6) double softmax + mask -> bf16 hi/lo probs
    softmax_mask_kernel<<<dim3(NN, BB), 256>>>(scores, mask, ph, pl);

    // 7) attn = P @ V  (B = V^T rows, K-major over keys)
    tc_gemm_kernel<false><<<dim3(DD / 128, NN / 128, BB), 256, GEMM_SMEM_BYTES>>>(
        ph, pl, vth, vtl, nullptr, attn, NN, NN, NN, DD, sSC, sVT, sQ, 1.0f);

    // 8) split attn
    split_kernel<<<(unsigned)(nTok * DD / 1024), 256>>>(attn, ath, atl, nTok * DD);

    // 9) out = attn @ W_out + b_out
    tc_gemm_kernel<true><<<dim3(DD / 128, (unsigned)(nTok / 128), 1), 256,
                           GEMM_SMEM_BYTES>>>(
        ath, atl, wot_h, wot_l, bout, out, DD, DD, DD, DD, 0, 0, 0, 1.0f);
}

// round 8
// speedup vs baseline: 2.4644x; 1.0079x over previous
#include <cuda_runtime.h>
#include <cuda_bf16.h>
#include <cstdint>
#include <cstring>
#include <math.h>

// ---------------------------------------------------------------------------
// SelfAttnV3  B=8, N=2048, D=1024
// HMMA (mma.sync bf16, 3-term split precision) GEMMs -- sm_103 base target.
// R8: 2 CTA/SM (96KB smem, <=128 regs), BK=32, 3-stage cp.async ring.
// ---------------------------------------------------------------------------
#define BB 8
#define NN 2048
#define DD 1024

// ------------------------- device scratch (no allocs) ----------------------
__device__ float g_qkv[(long long)BB * NN * 3 * DD];      // 192 MB
__device__ float g_scores[(long long)BB * NN * NN];       // 128 MB
__device__ float g_attn[(long long)BB * NN * DD];         // 64 MB

__device__ __nv_bfloat16 g_xh[(long long)BB * NN * DD];
__device__ __nv_bfloat16 g_xl[(long long)BB * NN * DD];
__device__ __nv_bfloat16 g_wqt_h[(long long)3 * DD * DD];
__device__ __nv_bfloat16 g_wqt_l[(long long)3 * DD * DD];
__device__ __nv_bfloat16 g_wot_h[(long long)DD * DD];
__device__ __nv_bfloat16 g_wot_l[(long long)DD * DD];
__device__ __nv_bfloat16 g_qh[(long long)BB * NN * DD];
__device__ __nv_bfloat16 g_ql[(long long)BB * NN * DD];
__device__ __nv_bfloat16 g_kh[(long long)BB * NN * DD];
__device__ __nv_bfloat16 g_kl[(long long)BB * NN * DD];
__device__ __nv_bfloat16 g_vth[(long long)BB * DD * NN];
__device__ __nv_bfloat16 g_vtl[(long long)BB * DD * NN];
__device__ __nv_bfloat16 g_ph[(long long)BB * NN * NN];
__device__ __nv_bfloat16 g_pl[(long long)BB * NN * NN];
__device__ __nv_bfloat16 g_ath[(long long)BB * NN * DD];
__device__ __nv_bfloat16 g_atl[(long long)BB * NN * DD];

// ------------------------------ PTX helpers --------------------------------
__device__ __forceinline__ uint32_t smem_u32(const void* p) {
    uint32_t a;
    asm("{ .reg .u64 t; cvta.to.shared.u64 t, %1; cvt.u32.u64 %0, t; }"
        : "=r"(a) : "l"(p));
    return a;
}

#define CP_ASYNC16(dst, src) \
    asm volatile("cp.async.cg.shared.global [%0], [%1], 16;" :: "r"(dst), "l"(src) : "memory")
#define CP_ASYNC_COMMIT() asm volatile("cp.async.commit_group;" ::: "memory")
#define CP_ASYNC_WAIT(n)  asm volatile("cp.async.wait_group %0;" :: "n"(n) : "memory")

__device__ __forceinline__ void ldsm4(uint32_t r[4], uint32_t addr) {
    asm volatile("ldmatrix.sync.aligned.m8n8.x4.shared.b16 {%0,%1,%2,%3}, [%4];"
                 : "=r"(r[0]), "=r"(r[1]), "=r"(r[2]), "=r"(r[3]) : "r"(addr));
}

__device__ __forceinline__ void mma_bf16(float c[4], const uint32_t a[4],
                                         uint32_t b0, uint32_t b1) {
    asm volatile(
        "mma.sync.aligned.m16n8k16.row.col.f32.bf16.bf16.f32 "
        "{%0,%1,%2,%3}, {%4,%5,%6,%7}, {%8,%9}, {%0,%1,%2,%3};"
        : "+f"(c[0]), "+f"(c[1]), "+f"(c[2]), "+f"(c[3])
        : "r"(a[0]), "r"(a[1]), "r"(a[2]), "r"(a[3]), "r"(b0), "r"(b1));
}

// ------------------------------ bf16 split helpers -------------------------
__device__ __forceinline__ void split4_store(__nv_bfloat16* ph, __nv_bfloat16* pl, float4 v)
{
    __nv_bfloat162 h01 = __floats2bfloat162_rn(v.x, v.y);
    __nv_bfloat162 h23 = __floats2bfloat162_rn(v.z, v.w);
    float2 f01 = __bfloat1622float2(h01);
    float2 f23 = __bfloat1622float2(h23);
    __nv_bfloat162 l01 = __floats2bfloat162_rn(v.x - f01.x, v.y - f01.y);
    __nv_bfloat162 l23 = __floats2bfloat162_rn(v.z - f23.x, v.w - f23.y);
    uint2 uh, ul;
    memcpy(&uh.x, &h01, 4); memcpy(&uh.y, &h23, 4);
    memcpy(&ul.x, &l01, 4); memcpy(&ul.y, &l23, 4);
    *reinterpret_cast<uint2*>(ph) = uh;
    *reinterpret_cast<uint2*>(pl) = ul;
}

// ---------------------------------------------------------------------------
// HMMA GEMM: C[M,N] (+bias) = alpha * A @ B^T with split-bf16 operands.
//   A: hi/lo bf16, M rows, K-major, ld = lda
//   B: hi/lo bf16, N rows, K-major, ld = ldb
// CTA tile 128x128, BK=32, 3-stage cp.async ring (32 KB/stage, 96 KB total).
// 8 warps: warp (wm = wid&3, wn = wid>>2) owns 32(m) x 64(n).
// Swizzle for 64B rows: cb ^ (((row>>1)&3)<<4)  (conflict-free ldmatrix).
// ---------------------------------------------------------------------------
#define STAGE_BYTES 32768
#define GEMM_SMEM_BYTES (3 * STAGE_BYTES)

__device__ __forceinline__ uint32_t sw64(int row, int cb) {
    return (uint32_t)(row * 64 + (cb ^ (((row >> 1) & 3) << 4)));
}

__device__ __forceinline__ void load_stage(uint32_t sbase,
    const __nv_bfloat16* Ah, const __nv_bfloat16* Al,
    const __nv_bfloat16* Bh, const __nv_bfloat16* Bl,
    int lda, int ldb, int k0, int tid)
{
#pragma unroll
    for (int i = 0; i < 2; i++) {
        const int idx = i * 256 + tid;          // 0..511
        const int row = idx >> 2;               // 0..127
        const int cb  = (idx & 3) << 4;         // 0,16,32,48
        const uint32_t soff = sw64(row, cb);
        const long long ea = (long long)row * lda + k0 + (cb >> 1);
        const long long eb = (long long)row * ldb + k0 + (cb >> 1);
        CP_ASYNC16(sbase +         soff, Ah + ea);
        CP_ASYNC16(sbase +  8192 + soff, Al + ea);
        CP_ASYNC16(sbase + 16384 + soff, Bh + eb);
        CP_ASYNC16(sbase + 24576 + soff, Bl + eb);
    }
}

template <bool HAS_BIAS>
__global__ void __launch_bounds__(256, 2)
tc_gemm_kernel(const __nv_bfloat16* __restrict__ Ah, const __nv_bfloat16* __restrict__ Al,
               const __nv_bfloat16* __restrict__ Bh, const __nv_bfloat16* __restrict__ Bl,
               const float* __restrict__ bias, float* __restrict__ C,
               int K, int lda, int ldb, int ldc,
               long long sA, long long sB, long long sC, float alpha)
{
    extern __shared__ char smem[];
    const uint32_t sb = smem_u32(smem);
    const int tid  = threadIdx.x;
    const int lane = tid & 31;
    const int wid  = tid >> 5;
    const int wm = wid & 3;        // 4 warps along M
    const int wn = wid >> 2;       // 2 warps along N

    const int bx = blockIdx.x, by = blockIdx.y, bz = blockIdx.z;
    const long long aOff = (long long)bz * sA + (long long)by * 128 * lda;
    const long long bOff = (long long)bz * sB + (long long)bx * 128 * ldb;
    Ah += aOff; Al += aOff; Bh += bOff; Bl += bOff;
    C  += (long long)bz * sC + (long long)by * 128 * ldc + (long long)bx * 128;

    float acc[2][8][4];
#pragma unroll
    for (int i = 0; i < 2; i++)
#pragma unroll
        for (int j = 0; j < 8; j++)
#pragma unroll
            for (int q = 0; q < 4; q++) acc[i][j][q] = 0.0f;

    const int T = K >> 5;

    load_stage(sb,               Ah, Al, Bh, Bl, lda, ldb,  0, tid);
    CP_ASYNC_COMMIT();
    load_stage(sb + STAGE_BYTES, Ah, Al, Bh, Bl, lda, ldb, 32, tid);
    CP_ASYNC_COMMIT();

    for (int t = 0; t < T; t++) {
        if (t + 2 < T) {
            int s2 = (t + 2) % 3;
            load_stage(sb + s2 * STAGE_BYTES, Ah, Al, Bh, Bl,
                       lda, ldb, (t + 2) << 5, tid);
        }
        CP_ASYNC_COMMIT();
        CP_ASYNC_WAIT(2);
        __syncthreads();

        const uint32_t st = sb + (t % 3) * STAGE_BYTES;
#pragma unroll
        for (int k16 = 0; k16 < 2; k16++) {
            const int cbase = k16 * 32 + ((lane >> 4) << 4);

            uint32_t ah[2][4], al[2][4], b[4][4];
            uint32_t offA[2], offB[4];
#pragma unroll
            for (int mt = 0; mt < 2; mt++) {
                const int row = wm * 32 + mt * 16 + (lane & 15);
                offA[mt] = sw64(row, cbase);
            }
#pragma unroll
            for (int ntp = 0; ntp < 4; ntp++) {
                const int row = wn * 64 + ntp * 16 + (lane & 15);
                offB[ntp] = sw64(row, cbase);
            }

            // hi*hi
#pragma unroll
            for (int mt = 0; mt < 2; mt++) ldsm4(ah[mt], st + offA[mt]);
#pragma unroll
            for (int ntp = 0; ntp < 4; ntp++) ldsm4(b[ntp], st + 16384 + offB[ntp]);
#pragma unroll
            for (int mt = 0; mt < 2; mt++)
#pragma unroll
                for (int ntp = 0; ntp < 4; ntp++)
#pragma unroll
                    for (int sub = 0; sub < 2; sub++)
                        mma_bf16(acc[mt][ntp * 2 + sub], ah[mt],
                                 b[ntp][sub], b[ntp][sub + 2]);

            // lo*hi (reuse b = Bh)
#pragma unroll
            for (int mt = 0; mt < 2; mt++) ldsm4(al[mt], st + 8192 + offA[mt]);
#pragma unroll
            for (int mt = 0; mt < 2; mt++)
#pragma unroll
                for (int ntp = 0; ntp < 4; ntp++)
#pragma unroll
                    for (int sub = 0; sub < 2; sub++)
                        mma_bf16(acc[mt][ntp * 2 + sub], al[mt],
                                 b[ntp][sub], b[ntp][sub + 2]);

            // hi*lo (overwrite b with Bl)
#pragma unroll
            for (int ntp = 0; ntp < 4; ntp++) ldsm4(b[ntp], st + 24576 + offB[ntp]);
#pragma unroll
            for (int mt = 0; mt < 2; mt++)
#pragma unroll
                for (int ntp = 0; ntp < 4; ntp++)
#pragma unroll
                    for (int sub = 0; sub < 2; sub++)
                        mma_bf16(acc[mt][ntp * 2 + sub], ah[mt],
                                 b[ntp][sub], b[ntp][sub + 2]);
        }
        __syncthreads();
    }

    // ---- epilogue ----
    const int rbase = wm * 32 + (lane >> 2);
    const int cbase = wn * 64 + (lane & 3) * 2;
#pragma unroll
    for (int mt = 0; mt < 2; mt++)
#pragma unroll
        for (int nt = 0; nt < 8; nt++) {
            const float* a = acc[mt][nt];
            const int m = rbase + mt * 16;
            const int n = cbase + nt * 8;
            float2 v0 = make_float2(a[0] * alpha, a[1] * alpha);
            float2 v1 = make_float2(a[2] * alpha, a[3] * alpha);
            if (HAS_BIAS) {
                const float b0 = bias[(long long)bx * 128 + n];
                const float b1 = bias[(long long)bx * 128 + n + 1];
                v0.x += b0; v0.y += b1; v1.x += b0; v1.y += b1;
            }
            *reinterpret_cast<float2*>(&C[(long long)m * ldc + n]) = v0;
            *reinterpret_cast<float2*>(&C[(long long)(m + 8) * ldc + n]) = v1;
        }
}

// ---------------------------------------------------------------------------
// elementwise fp32 -> bf16 hi/lo split
// ---------------------------------------------------------------------------
__global__ void __launch_bounds__(256)
split_kernel(const float* __restrict__ in, __nv_bfloat16* __restrict__ oh,
             __nv_bfloat16* __restrict__ ol, long long n)
{
    const long long i = ((long long)blockIdx.x * 256 + threadIdx.x) * 4;
    if (i >= n) return;
    const float4 v = *reinterpret_cast<const float4*>(&in[i]);
    split4_store(oh + i, ol + i, v);
}

// ---------------------------------------------------------------------------
// transpose + split: out[c][r] = in[r][c]; out hi/lo bf16
// ---------------------------------------------------------------------------
__global__ void __launch_bounds__(256)
transpose_split_kernel(const float* __restrict__ in, int ld_in, long long strideIn,
                       __nv_bfloat16* __restrict__ oh, __nv_bfloat16* __restrict__ ol,
                       int ld_out, long long strideOut)
{
    __shared__ float t[32][33];
    const int bz = blockIdx.z;
    in += (long long)bz * strideIn;
    oh += (long long)bz * strideOut;
    ol += (long long)bz * strideOut;
    const int tx = threadIdx.x & 31, ty = threadIdx.x >> 5;
    const int r0 = blockIdx.y * 32, c0 = blockIdx.x * 32;
#pragma unroll
    for (int i = 0; i < 4; i++)
        t[ty + i * 8][tx] = in[(long long)(r0 + ty + i * 8) * ld_in + c0 + tx];
    __syncthreads();
#pragma unroll
    for (int i = 0; i < 4; i++) {
        const int oc = ty + i * 8;
        const float v = t[tx][oc];
        const __nv_bfloat16 h = __float2bfloat16_rn(v);
        const long long o = (long long)(c0 + oc) * ld_out + r0 + tx;
        oh[o] = h;
        ol[o] = __float2bfloat16_rn(v - __bfloat162float(h));
    }
}

// ---------------------------------------------------------------------------
// split Q,K rows out of qkv fp32 (row = b*N+n, 3072 wide)
// ---------------------------------------------------------------------------
__global__ void __launch_bounds__(256)
qk_split_kernel(const float* __restrict__ qkv,
                __nv_bfloat16* __restrict__ Qh, __nv_bfloat16* __restrict__ Ql,
                __nv_bfloat16* __restrict__ Kh, __nv_bfloat16* __restrict__ Kl)
{
    const long long row = blockIdx.x;
    const float* src = qkv + row * 3 * DD;
    const int idx = threadIdx.x * 4;
    const float4 q  = *reinterpret_cast<const float4*>(&src[idx]);
    const float4 kk = *reinterpret_cast<const float4*>(&src[DD + idx]);
    split4_store(Qh + row * DD + idx, Ql + row * DD + idx, q);
    split4_store(Kh + row * DD + idx, Kl + row * DD + idx, kk);
}

// ---------------------------------------------------------------------------
// fused double-softmax with mask; outputs bf16 hi/lo probs
// ---------------------------------------------------------------------------
__device__ __forceinline__ float warpMax(float v) {
#pragma unroll
    for (int o = 16; o > 0; o >>= 1) v = fmaxf(v, __shfl_xor_sync(0xffffffffu, v, o));
    return v;
}
__device__ __forceinline__ float warpSum(float v) {
#pragma unroll
    for (int o = 16; o > 0; o >>= 1) v += __shfl_xor_sync(0xffffffffu, v, o);
    return v;
}
__device__ __forceinline__ float blockMax(float v, float* s) {
    const int w = threadIdx.x >> 5, l = threadIdx.x & 31;
    v = warpMax(v);
    __syncthreads();
    if (l == 0) s[w] = v;
    __syncthreads();
    float r = s[0];
#pragma unroll
    for (int i = 1; i < 8; i++) r = fmaxf(r, s[i]);
    return r;
}
__device__ __forceinline__ float blockSum(float v, float* s) {
    const int w = threadIdx.x >> 5, l = threadIdx.x & 31;
    v = warpSum(v);
    __syncthreads();
    if (l == 0) s[w] = v;
    __syncthreads();
    float r = s[0];
#pragma unroll
    for (int i = 1; i < 8; i++) r += s[i];
    return r;
}

__global__ __launch_bounds__(256)
void softmax_mask_kernel(const float* __restrict__ S, const int* __restrict__ mask,
                         __nv_bfloat16* __restrict__ Ph, __nv_bfloat16* __restrict__ Pl)
{
    __shared__ float red[8];

    const long long row = (long long)blockIdx.y * NN + blockIdx.x;
    const float* srow = S + row * NN;
    const int* mrow = mask + row * NN;
    const int base = threadIdx.x * 8;

    float v[8];
    *reinterpret_cast<float4*>(&v[0]) = *reinterpret_cast<const float4*>(&srow[base]);
    *reinterpret_cast<float4*>(&v[4]) = *reinterpret_cast<const float4*>(&srow[base + 4]);

    float m = v[0];
#pragma unroll
    for (int i = 1; i < 8; i++) m = fmaxf(m, v[i]);
    m = blockMax(m, red);

    float p[8], lsum = 0.0f;
#pragma unroll
    for (int i = 0; i < 8; i++) { p[i] = __expf(v[i] - m); lsum += p[i]; }
    const float inv1 = 1.0f / blockSum(lsum, red);
#pragma unroll
    for (int i = 0; i < 8; i++) p[i] *= inv1;

    int mk[8];
    *reinterpret_cast<int4*>(&mk[0]) = *reinterpret_cast<const int4*>(&mrow[base]);
    *reinterpret_cast<int4*>(&mk[4]) = *reinterpret_cast<const int4*>(&mrow[base + 4]);

    float m2 = -3.0e38f;
#pragma unroll
    for (int i = 0; i < 8; i++) if (mk[i] != 0) m2 = fmaxf(m2, p[i]);
    m2 = blockMax(m2, red);

    float t[8], lsum2 = 0.0f;
#pragma unroll
    for (int i = 0; i < 8; i++) {
        t[i] = (mk[i] != 0) ? __expf(p[i] - m2) : 0.0f;
        lsum2 += t[i];
    }
    const float inv2 = 1.0f / blockSum(lsum2, red);

    float w[8];
#pragma unroll
    for (int i = 0; i < 8; i++) w[i] = t[i] * inv2;

    __nv_bfloat16* ph = Ph + row * NN + base;
    __nv_bfloat16* pl = Pl + row * NN + base;
    split4_store(ph,     pl,     *reinterpret_cast<float4*>(&w[0]));
    split4_store(ph + 4, pl + 4, *reinterpret_cast<float4*>(&w[4]));
}

// ---------------------------------------------------------------------------
// Launch
// ---------------------------------------------------------------------------
extern "C" void kernel_launch(void* const* d_in, const int* in_sizes, int n_in,
                              void* d_out, int out_size)
{
    (void)in_sizes; (void)n_in; (void)out_size;

    const float* x    = (const float*)d_in[0];
    const int*   mask = (const int*)  d_in[1];
    const float* Wqkv = (const float*)d_in[2];
    const float* bqkv = (const float*)d_in[3];
    const float* Wout = (const float*)d_in[4];
    const float* bout = (const float*)d_in[5];
    float* out = (float*)d_out;

    cudaFuncSetAttribute(tc_gemm_kernel<true>,
                         cudaFuncAttributeMaxDynamicSharedMemorySize, GEMM_SMEM_BYTES);
    cudaFuncSetAttribute(tc_gemm_kernel<false>,
                         cudaFuncAttributeMaxDynamicSharedMemorySize, GEMM_SMEM_BYTES);

    float *qkv, *scores, *attn;
    cudaGetSymbolAddress((void**)&qkv,    g_qkv);
    cudaGetSymbolAddress((void**)&scores, g_scores);
    cudaGetSymbolAddress((void**)&attn,   g_attn);
    __nv_bfloat16 *xh, *xl, *wqt_h, *wqt_l, *wot_h, *wot_l;
    __nv_bfloat16 *qh, *ql, *kh, *kl, *vth, *vtl, *ph, *pl, *ath, *atl;
    cudaGetSymbolAddress((void**)&xh, g_xh);     cudaGetSymbolAddress((void**)&xl, g_xl);
    cudaGetSymbolAddress((void**)&wqt_h, g_wqt_h); cudaGetSymbolAddress((void**)&wqt_l, g_wqt_l);
    cudaGetSymbolAddress((void**)&wot_h, g_wot_h); cudaGetSymbolAddress((void**)&wot_l, g_wot_l);
    cudaGetSymbolAddress((void**)&qh, g_qh);     cudaGetSymbolAddress((void**)&ql, g_ql);
    cudaGetSymbolAddress((void**)&kh, g_kh);     cudaGetSymbolAddress((void**)&kl, g_kl);
    cudaGetSymbolAddress((void**)&vth, g_vth);   cudaGetSymbolAddress((void**)&vtl, g_vtl);
    cudaGetSymbolAddress((void**)&ph, g_ph);     cudaGetSymbolAddress((void**)&pl, g_pl);
    cudaGetSymbolAddress((void**)&ath, g_ath);   cudaGetSymbolAddress((void**)&atl, g_atl);

    const long long nTok = (long long)BB * NN;           // 16384
    const long long sQ   = (long long)NN * DD;
    const long long sSC  = (long long)NN * NN;
    const long long sVT  = (long long)DD * NN;

    // 1) split x -> bf16 hi/lo
    split_kernel<<<(unsigned)(nTok * DD / 1024), 256>>>(x, xh, xl, nTok * DD);

    // 2) transpose+split weights
    transpose_split_kernel<<<dim3(3 * DD / 32, DD / 32, 1), 256>>>(
        Wqkv, 3 * DD, 0, wqt_h, wqt_l, DD, 0);
    transpose_split_kernel<<<dim3(DD / 32, DD / 32, 1), 256>>>(
        Wout, DD, 0, wot_h, wot_l, DD, 0);

    // 3) qkv = x @ W_qkv + b_qkv  (fp32 out)
    tc_gemm_kernel<true><<<dim3(3 * DD / 128, (unsigned)(nTok / 128), 1), 256,
                           GEMM_SMEM_BYTES>>>(
        xh, xl, wqt_h, wqt_l, bqkv, qkv, DD, DD, DD, 3 * DD, 0, 0, 0, 1.0f);

    // 4) split Q,K (K-major) and V (transposed)
    qk_split_kernel<<<(unsigned)nTok, 256>>>(qkv, qh, ql, kh, kl);
    transpose_split_kernel<<<dim3(DD / 32, NN / 32, BB), 256>>>(
        qkv + 2 * DD, 3 * DD, (long long)NN * 3 * DD, vth, vtl, NN, sVT);

    // 5) scores = Q @ K^T / 32  (fp32 out)
    tc_gemm_kernel<false><<<dim3(NN / 128, NN / 128, BB), 256, GEMM_SMEM_BYTES>>>(
        qh, ql, kh, kl, nullptr, scores, DD, DD, DD, NN, sQ, sQ, sSC, 0.03125f);

    // 6) double softmax + mask -> bf16 hi/lo probs
    softmax_mask_kernel<<<dim3(NN, BB), 256>>>(scores, mask, ph, pl);

    // 7) attn = P @ V  (B = V^T rows, K-major over keys)
    tc_gemm_kernel<false><<<dim3(DD / 128, NN / 128, BB), 256, GEMM_SMEM_BYTES>>>(
        ph, pl, vth, vtl, nullptr, attn, NN, NN, NN, DD, sSC, sVT, sQ, 1.0f);

    // 8) split attn
    split_kernel<<<(unsigned)(nTok * DD / 1024), 256>>>(attn, ath, atl, nTok * DD);

    // 9) out = attn @ W_out + b_out
    tc_gemm_kernel<true><<<dim3(DD / 128, (unsigned)(nTok / 128), 1), 256,
                           GEMM_SMEM_BYTES>>>(
        ath, atl, wot_h, wot_l, bout, out, DD, DD, DD, DD, 0, 0, 0, 1.0f);
}

// round 14
// speedup vs baseline: 3.5301x; 1.4324x over previous
#include <cuda_runtime.h>
#include <cuda_fp16.h>
#include <cstdint>
#include <cstring>
#include <math.h>

// ---------------------------------------------------------------------------
// SelfAttnV3  B=8, N=2048, D=1024
// HMMA fp16 2-term split GEMMs (A truncated to fp16, B split hi/lo fp16).
//   C = A@B^T  ~=  Ah@Bh^T + Ah@Bl^T      (error ~2^-11/sqrt(3) per GEMM)
// R12: PV GEMM writes fp16 directly (OUT_HALF epilogue) -- one less pass.
// ---------------------------------------------------------------------------
#define BB 8
#define NN 2048
#define DD 1024

// ------------------------- device scratch (no allocs) ----------------------
__device__ float g_qkv[(long long)BB * NN * 3 * DD];      // 192 MB
__device__ float g_scores[(long long)BB * NN * NN];       // 128 MB

__device__ __half g_xh[(long long)BB * NN * DD];          // A sides (single)
__device__ __half g_qh[(long long)BB * NN * DD];
__device__ __half g_ph[(long long)BB * NN * NN];
__device__ __half g_ath[(long long)BB * NN * DD];

__device__ __half g_wqt_h[(long long)3 * DD * DD];        // B sides (split)
__device__ __half g_wqt_l[(long long)3 * DD * DD];
__device__ __half g_wot_h[(long long)DD * DD];
__device__ __half g_wot_l[(long long)DD * DD];
__device__ __half g_kh[(long long)BB * NN * DD];
__device__ __half g_kl[(long long)BB * NN * DD];
__device__ __half g_vth[(long long)BB * DD * NN];
__device__ __half g_vtl[(long long)BB * DD * NN];

// ------------------------------ PTX helpers --------------------------------
__device__ __forceinline__ uint32_t smem_u32(const void* p) {
    uint32_t a;
    asm("{ .reg .u64 t; cvta.to.shared.u64 t, %1; cvt.u32.u64 %0, t; }"
        : "=r"(a) : "l"(p));
    return a;
}

#define CP_ASYNC16(dst, src) \
    asm volatile("cp.async.cg.shared.global [%0], [%1], 16;" :: "r"(dst), "l"(src) : "memory")
#define CP_ASYNC_COMMIT() asm volatile("cp.async.commit_group;" ::: "memory")
#define CP_ASYNC_WAIT(n)  asm volatile("cp.async.wait_group %0;" :: "n"(n) : "memory")

__device__ __forceinline__ void ldsm4(uint32_t r[4], uint32_t addr) {
    asm volatile("ldmatrix.sync.aligned.m8n8.x4.shared.b16 {%0,%1,%2,%3}, [%4];"
                 : "=r"(r[0]), "=r"(r[1]), "=r"(r[2]), "=r"(r[3]) : "r"(addr));
}

__device__ __forceinline__ void mma_f16(float c[4], const uint32_t a[4],
                                        uint32_t b0, uint32_t b1) {
    asm volatile(
        "mma.sync.aligned.m16n8k16.row.col.f32.f16.f16.f32 "
        "{%0,%1,%2,%3}, {%4,%5,%6,%7}, {%8,%9}, {%0,%1,%2,%3};"
        : "+f"(c[0]), "+f"(c[1]), "+f"(c[2]), "+f"(c[3])
        : "r"(a[0]), "r"(a[1]), "r"(a[2]), "r"(a[3]), "r"(b0), "r"(b1));
}

// ------------------------------ fp16 helpers -------------------------------
__device__ __forceinline__ void cvt4_half(__half* dst, float4 v) {
    __half2 h01 = __floats2half2_rn(v.x, v.y);
    __half2 h23 = __floats2half2_rn(v.z, v.w);
    *reinterpret_cast<__half2*>(dst)     = h01;
    *reinterpret_cast<__half2*>(dst + 2) = h23;
}

__device__ __forceinline__ void split4_half(__half* ph, __half* pl, float4 v) {
    __half2 h01 = __floats2half2_rn(v.x, v.y);
    __half2 h23 = __floats2half2_rn(v.z, v.w);
    float2 f01 = __half22float2(h01);
    float2 f23 = __half22float2(h23);
    __half2 l01 = __floats2half2_rn(v.x - f01.x, v.y - f01.y);
    __half2 l23 = __floats2half2_rn(v.z - f23.x, v.w - f23.y);
    *reinterpret_cast<__half2*>(ph)     = h01;
    *reinterpret_cast<__half2*>(ph + 2) = h23;
    *reinterpret_cast<__half2*>(pl)     = l01;
    *reinterpret_cast<__half2*>(pl + 2) = l23;
}

// ---------------------------------------------------------------------------
// HMMA GEMM: C[M,N] (+bias) = alpha * (Ah @ (Bh+Bl)^T)
//   Ah: fp16, M rows, K-major, ld = lda
//   Bh/Bl: fp16, N rows, K-major, ld = ldb
//   C: fp32 (OUT_HALF=0) or fp16 (OUT_HALF=1)
// CTA tile 128x128, BK=32, 3-stage cp.async ring (24 KB/stage, 72 KB).
// 8 warps: warp (wm = wid&3, wn = wid>>2) owns 32(m) x 64(n).
// Swizzle for 64B rows: cb ^ (((row>>1)&3)<<4)  (conflict-free ldmatrix).
// ---------------------------------------------------------------------------
#define STAGE_BYTES 24576
#define GEMM_SMEM_BYTES (3 * STAGE_BYTES)

__device__ __forceinline__ uint32_t sw64(int row, int cb) {
    return (uint32_t)(row * 64 + (cb ^ (((row >> 1) & 3) << 4)));
}

__device__ __forceinline__ void load_stage(uint32_t sbase,
    const __half* Ah, const __half* Bh, const __half* Bl,
    int lda, int ldb, int k0, int tid)
{
#pragma unroll
    for (int i = 0; i < 2; i++) {
        const int idx = i * 256 + tid;          // 0..511
        const int row = idx >> 2;               // 0..127
        const int cb  = (idx & 3) << 4;         // 0,16,32,48
        const uint32_t soff = sw64(row, cb);
        const long long ea = (long long)row * lda + k0 + (cb >> 1);
        const long long eb = (long long)row * ldb + k0 + (cb >> 1);
        CP_ASYNC16(sbase +         soff, Ah + ea);
        CP_ASYNC16(sbase +  8192 + soff, Bh + eb);
        CP_ASYNC16(sbase + 16384 + soff, Bl + eb);
    }
}

template <bool HAS_BIAS, bool OUT_HALF>
__global__ void __launch_bounds__(256, 2)
tc_gemm_kernel(const __half* __restrict__ Ah,
               const __half* __restrict__ Bh, const __half* __restrict__ Bl,
               const float* __restrict__ bias, void* __restrict__ Cv,
               int K, int lda, int ldb, int ldc,
               long long sA, long long sB, long long sC, float alpha)
{
    extern __shared__ char smem[];
    const uint32_t sb = smem_u32(smem);
    const int tid  = threadIdx.x;
    const int lane = tid & 31;
    const int wid  = tid >> 5;
    const int wm = wid & 3;        // 4 warps along M
    const int wn = wid >> 2;       // 2 warps along N

    const int bx = blockIdx.x, by = blockIdx.y, bz = blockIdx.z;
    const long long aOff = (long long)bz * sA + (long long)by * 128 * lda;
    const long long bOff = (long long)bz * sB + (long long)bx * 128 * ldb;
    Ah += aOff; Bh += bOff; Bl += bOff;
    const long long cOff = (long long)bz * sC + (long long)by * 128 * ldc
                         + (long long)bx * 128;

    float acc[2][8][4];
#pragma unroll
    for (int i = 0; i < 2; i++)
#pragma unroll
        for (int j = 0; j < 8; j++)
#pragma unroll
            for (int q = 0; q < 4; q++) acc[i][j][q] = 0.0f;

    // hoisted fragment smem offsets (k16 = 0; k16 = 1 is XOR 32)
    const int cb0 = (lane >> 4) << 4;
    uint32_t offA[2], offB[4];
#pragma unroll
    for (int mt = 0; mt < 2; mt++)
        offA[mt] = sw64(wm * 32 + mt * 16 + (lane & 15), cb0);
#pragma unroll
    for (int ntp = 0; ntp < 4; ntp++)
        offB[ntp] = sw64(wn * 64 + ntp * 16 + (lane & 15), cb0);

    const int T = K >> 5;

    load_stage(sb,               Ah, Bh, Bl, lda, ldb,  0, tid);
    CP_ASYNC_COMMIT();
    load_stage(sb + STAGE_BYTES, Ah, Bh, Bl, lda, ldb, 32, tid);
    CP_ASYNC_COMMIT();

    for (int t = 0; t < T; t++) {
        if (t + 2 < T) {
            int s2 = (t + 2) % 3;
            load_stage(sb + s2 * STAGE_BYTES, Ah, Bh, Bl,
                       lda, ldb, (t + 2) << 5, tid);
        }
        CP_ASYNC_COMMIT();
        CP_ASYNC_WAIT(2);
        __syncthreads();

        const uint32_t st = sb + (t % 3) * STAGE_BYTES;
#pragma unroll
        for (int k16 = 0; k16 < 2; k16++) {
            const uint32_t xk = (uint32_t)(k16 << 5);

            uint32_t ah[2][4], b[4][4];
#pragma unroll
            for (int mt = 0; mt < 2; mt++) ldsm4(ah[mt], st + (offA[mt] ^ xk));

            // term 1: Ah x Bh
#pragma unroll
            for (int ntp = 0; ntp < 4; ntp++)
                ldsm4(b[ntp], st + 8192 + (offB[ntp] ^ xk));
#pragma unroll
            for (int mt = 0; mt < 2; mt++)
#pragma unroll
                for (int ntp = 0; ntp < 4; ntp++)
#pragma unroll
                    for (int sub = 0; sub < 2; sub++)
                        mma_f16(acc[mt][ntp * 2 + sub], ah[mt],
                                b[ntp][sub], b[ntp][sub + 2]);

            // term 2: Ah x Bl (overwrite b)
#pragma unroll
            for (int ntp = 0; ntp < 4; ntp++)
                ldsm4(b[ntp], st + 16384 + (offB[ntp] ^ xk));
#pragma unroll
            for (int mt = 0; mt < 2; mt++)
#pragma unroll
                for (int ntp = 0; ntp < 4; ntp++)
#pragma unroll
                    for (int sub = 0; sub < 2; sub++)
                        mma_f16(acc[mt][ntp * 2 + sub], ah[mt],
                                b[ntp][sub], b[ntp][sub + 2]);
        }
        __syncthreads();
    }

    // ---- epilogue ----
    const int rbase = wm * 32 + (lane >> 2);
    const int cbase = wn * 64 + (lane & 3) * 2;
#pragma unroll
    for (int mt = 0; mt < 2; mt++)
#pragma unroll
        for (int nt = 0; nt < 8; nt++) {
            const float* a = acc[mt][nt];
            const int m = rbase + mt * 16;
            const int n = cbase + nt * 8;
            float2 v0 = make_float2(a[0] * alpha, a[1] * alpha);
            float2 v1 = make_float2(a[2] * alpha, a[3] * alpha);
            if (HAS_BIAS) {
                const float b0 = bias[(long long)bx * 128 + n];
                const float b1 = bias[(long long)bx * 128 + n + 1];
                v0.x += b0; v0.y += b1; v1.x += b0; v1.y += b1;
            }
            if (OUT_HALF) {
                __half* C = (__half*)Cv + cOff;
                *reinterpret_cast<__half2*>(&C[(long long)m * ldc + n]) =
                    __floats2half2_rn(v0.x, v0.y);
                *reinterpret_cast<__half2*>(&C[(long long)(m + 8) * ldc + n]) =
                    __floats2half2_rn(v1.x, v1.y);
            } else {
                float* C = (float*)Cv + cOff;
                *reinterpret_cast<float2*>(&C[(long long)m * ldc + n]) = v0;
                *reinterpret_cast<float2*>(&C[(long long)(m + 8) * ldc + n]) = v1;
            }
        }
}

// ---------------------------------------------------------------------------
// elementwise fp32 -> single fp16
// ---------------------------------------------------------------------------
__global__ void __launch_bounds__(256)
cvt_half_kernel(const float* __restrict__ in, __half* __restrict__ oh, long long n)
{
    const long long i = ((long long)blockIdx.x * 256 + threadIdx.x) * 4;
    if (i >= n) return;
    cvt4_half(oh + i, *reinterpret_cast<const float4*>(&in[i]));
}

// ---------------------------------------------------------------------------
// transpose + split: out[c][r] = in[r][c]; out hi/lo fp16
// ---------------------------------------------------------------------------
__global__ void __launch_bounds__(256)
transpose_split_kernel(const float* __restrict__ in, int ld_in, long long strideIn,
                       __half* __restrict__ oh, __half* __restrict__ ol,
                       int ld_out, long long strideOut)
{
    __shared__ float t[32][33];
    const int bz = blockIdx.z;
    in += (long long)bz * strideIn;
    oh += (long long)bz * strideOut;
    ol += (long long)bz * strideOut;
    const int tx = threadIdx.x & 31, ty = threadIdx.x >> 5;
    const int r0 = blockIdx.y * 32, c0 = blockIdx.x * 32;
#pragma unroll
    for (int i = 0; i < 4; i++)
        t[ty + i * 8][tx] = in[(long long)(r0 + ty + i * 8) * ld_in + c0 + tx];
    __syncthreads();
#pragma unroll
    for (int i = 0; i < 4; i++) {
        const int oc = ty + i * 8;
        const float v = t[tx][oc];
        const __half h = __float2half_rn(v);
        const long long o = (long long)(c0 + oc) * ld_out + r0 + tx;
        oh[o] = h;
        ol[o] = __float2half_rn(v - __half2float(h));
    }
}

// ---------------------------------------------------------------------------
// split Q (single) and K (hi/lo) rows out of qkv fp32
// ---------------------------------------------------------------------------
__global__ void __launch_bounds__(256)
qk_split_kernel(const float* __restrict__ qkv,
                __half* __restrict__ Qh,
                __half* __restrict__ Kh, __half* __restrict__ Kl)
{
    const long long row = blockIdx.x;
    const float* src = qkv + row * 3 * DD;
    const int idx = threadIdx.x * 4;
    const float4 q  = *reinterpret_cast<const float4*>(&src[idx]);
    const float4 kk = *reinterpret_cast<const float4*>(&src[DD + idx]);
    cvt4_half(Qh + row * DD + idx, q);
    split4_half(Kh + row * DD + idx, Kl + row * DD + idx, kk);
}

// ---------------------------------------------------------------------------
// fused double-softmax with mask; outputs single fp16 probs
// ---------------------------------------------------------------------------
__device__ __forceinline__ float warpMax(float v) {
#pragma unroll
    for (int o = 16; o > 0; o >>= 1) v = fmaxf(v, __shfl_xor_sync(0xffffffffu, v, o));
    return v;
}
__device__ __forceinline__ float warpSum(float v) {
#pragma unroll
    for (int o = 16; o > 0; o >>= 1) v += __shfl_xor_sync(0xffffffffu, v, o);
    return v;
}
__device__ __forceinline__ float blockMax(float v, float* s) {
    const int w = threadIdx.x >> 5, l = threadIdx.x & 31;
    v = warpMax(v);
    __syncthreads();
    if (l == 0) s[w] = v;
    __syncthreads();
    float r = s[0];
#pragma unroll
    for (int i = 1; i < 8; i++) r = fmaxf(r, s[i]);
    return r;
}
__device__ __forceinline__ float blockSum(float v, float* s) {
    const int w = threadIdx.x >> 5, l = threadIdx.x & 31;
    v = warpSum(v);
    __syncthreads();
    if (l == 0) s[w] = v;
    __syncthreads();
    float r = s[0];
#pragma unroll
    for (int i = 1; i < 8; i++) r += s[i];
    return r;
}

__global__ __launch_bounds__(256)
void softmax_mask_kernel(const float* __restrict__ S, const int* __restrict__ mask,
                         __half* __restrict__ Ph)
{
    __shared__ float red[8];

    const long long row = (long long)blockIdx.y * NN + blockIdx.x;
    const float* srow = S + row * NN;
    const int* mrow = mask + row * NN;
    const int base = threadIdx.x * 8;

    float v[8];
    *reinterpret_cast<float4*>(&v[0]) = *reinterpret_cast<const float4*>(&srow[base]);
    *reinterpret_cast<float4*>(&v[4]) = *reinterpret_cast<const float4*>(&srow[base + 4]);

    float m = v[0];
#pragma unroll
    for (int i = 1; i < 8; i++) m = fmaxf(m, v[i]);
    m = blockMax(m, red);

    float p[8], lsum = 0.0f;
#pragma unroll
    for (int i = 0; i < 8; i++) { p[i] = __expf(v[i] - m); lsum += p[i]; }
    const float inv1 = 1.0f / blockSum(lsum, red);
#pragma unroll
    for (int i = 0; i < 8; i++) p[i] *= inv1;

    int mk[8];
    *reinterpret_cast<int4*>(&mk[0]) = *reinterpret_cast<const int4*>(&mrow[base]);
    *reinterpret_cast<int4*>(&mk[4]) = *reinterpret_cast<const int4*>(&mrow[base + 4]);

    float m2 = -3.0e38f;
#pragma unroll
    for (int i = 0; i < 8; i++) if (mk[i] != 0) m2 = fmaxf(m2, p[i]);
    m2 = blockMax(m2, red);

    float t[8], lsum2 = 0.0f;
#pragma unroll
    for (int i = 0; i < 8; i++) {
        t[i] = (mk[i] != 0) ? __expf(p[i] - m2) : 0.0f;
        lsum2 += t[i];
    }
    const float inv2 = 1.0f / blockSum(lsum2, red);

    float w[8];
#pragma unroll
    for (int i = 0; i < 8; i++) w[i] = t[i] * inv2;

    __half* ph = Ph + row * NN + base;
    cvt4_half(ph,     *reinterpret_cast<float4*>(&w[0]));
    cvt4_half(ph + 4, *reinterpret_cast<float4*>(&w[4]));
}

// ---------------------------------------------------------------------------
// Launch
// ---------------------------------------------------------------------------
extern "C" void kernel_launch(void* const* d_in, const int* in_sizes, int n_in,
                              void* d_out, int out_size)
{
    (void)in_sizes; (void)n_in; (void)out_size;

    const float* x    = (const float*)d_in[0];
    const int*   mask = (const int*)  d_in[1];
    const float* Wqkv = (const float*)d_in[2];
    const float* bqkv = (const float*)d_in[3];
    const float* Wout = (const float*)d_in[4];
    const float* bout = (const float*)d_in[5];
    float* out = (float*)d_out;

    cudaFuncSetAttribute(tc_gemm_kernel<true, false>,
                         cudaFuncAttributeMaxDynamicSharedMemorySize, GEMM_SMEM_BYTES);
    cudaFuncSetAttribute(tc_gemm_kernel<false, false>,
                         cudaFuncAttributeMaxDynamicSharedMemorySize, GEMM_SMEM_BYTES);
    cudaFuncSetAttribute(tc_gemm_kernel<false, true>,
                         cudaFuncAttributeMaxDynamicSharedMemorySize, GEMM_SMEM_BYTES);

    float *qkv, *scores;
    cudaGetSymbolAddress((void**)&qkv,    g_qkv);
    cudaGetSymbolAddress((void**)&scores, g_scores);
    __half *xh, *qh, *ph, *ath;
    __half *wqt_h, *wqt_l, *wot_h, *wot_l, *kh, *kl, *vth, *vtl;
    cudaGetSymbolAddress((void**)&xh, g_xh);
    cudaGetSymbolAddress((void**)&qh, g_qh);
    cudaGetSymbolAddress((void**)&ph, g_ph);
    cudaGetSymbolAddress((void**)&ath, g_ath);
    cudaGetSymbolAddress((void**)&wqt_h, g_wqt_h);
    cudaGetSymbolAddress((void**)&wqt_l, g_wqt_l);
    cudaGetSymbolAddress((void**)&wot_h, g_wot_h);
    cudaGetSymbolAddress((void**)&wot_l, g_wot_l);
    cudaGetSymbolAddress((void**)&kh, g_kh);
    cudaGetSymbolAddress((void**)&kl, g_kl);
    cudaGetSymbolAddress((void**)&vth, g_vth);
    cudaGetSymbolAddress((void**)&vtl, g_vtl);

    const long long nTok = (long long)BB * NN;           // 16384
    const long long sQ   = (long long)NN * DD;
    const long long sSC  = (long long)NN * NN;
    const long long sVT  = (long long)DD * NN;

    // 1) x -> fp16 (A side, single)
    cvt_half_kernel<<<(unsigned)(nTok * DD / 1024), 256>>>(x, xh, nTok * DD);

    // 2) transpose+split weights (B sides)
    transpose_split_kernel<<<dim3(3 * DD / 32, DD / 32, 1), 256>>>(
        Wqkv, 3 * DD, 0, wqt_h, wqt_l, DD, 0);
    transpose_split_kernel<<<dim3(DD / 32, DD / 32, 1), 256>>>(
        Wout, DD, 0, wot_h, wot_l, DD, 0);

    // 3) qkv = x @ W_qkv + b_qkv  (fp32 out)
    tc_gemm_kernel<true, false><<<dim3(3 * DD / 128, (unsigned)(nTok / 128), 1), 256,
                                  GEMM_SMEM_BYTES>>>(
        xh, wqt_h, wqt_l, bqkv, qkv, DD, DD, DD, 3 * DD, 0, 0, 0, 1.0f);

    // 4) Q (single) / K (split) ; V transposed (split)
    qk_split_kernel<<<(unsigned)nTok, 256>>>(qkv, qh, kh, kl);
    transpose_split_kernel<<<dim3(DD / 32, NN / 32, BB), 256>>>(
        qkv + 2 * DD, 3 * DD, (long long)NN * 3 * DD, vth, vtl, NN, sVT);

    // 5) scores = Q @ K^T / 32  (fp32 out)
    tc_gemm_kernel<false, false><<<dim3(NN / 128, NN / 128, BB), 256,
                                   GEMM_SMEM_BYTES>>>(
        qh, kh, kl, nullptr, scores, DD, DD, DD, NN, sQ, sQ, sSC, 0.03125f);

    // 6) double softmax + mask -> fp16 probs
    softmax_mask_kernel<<<dim3(NN, BB), 256>>>(scores, mask, ph);

    // 7) attn = P @ V  (fp16 out, straight into the next GEMM's A side)
    tc_gemm_kernel<false, true><<<dim3(DD / 128, NN / 128, BB), 256,
                                  GEMM_SMEM_BYTES>>>(
        ph, vth, vtl, nullptr, ath, NN, NN, NN, DD, sSC, sVT, sQ, 1.0f);

    // 8) out = attn @ W_out + b_out  (fp32 out)
    tc_gemm_kernel<true, false><<<dim3(DD / 128, (unsigned)(nTok / 128), 1), 256,
                                  GEMM_SMEM_BYTES>>>(
        ath, wot_h, wot_l, bout, out, DD, DD, DD, DD, 0, 0, 0, 1.0f);
}